// round 17
// baseline (speedup 1.0000x reference)
#include <cuda_runtime.h>
#include <cuda_fp16.h>
#include <cstdint>
#include <cstddef>

// ============================================================================
// Problem constants
// ============================================================================
#define GROUPS 8
#define TOKENS 16384
#define IN_F   1024
#define OUT_F  1024

// GEMM tiling: CTA 128x128x64, 8 warps (2x4), warp tile 64x32, mma m16n8k16
// 3-stage cp.async pipeline, 2 CTA/SM -> 4 warps/SMSP from 2 independent CTAs
#define BM 128
#define BN 128
#define BK 64
#define NCHUNKS (IN_F / BK)          // 16
#define THREADS 256

#define M_TILES (TOKENS / BM)        // 128
#define N_TILES (OUT_F / BN)         // 8

// SMEM stage layout, fragment-order fp16 (identical to R13/R15):
// A: [8 m16blk][4 ks][32 lane] x 16B = 16384B  (frag = 1 LDS.128/lane)
// B: [2 kp][16 n8][32 lane] x 16B = 16384B     (16B = 2 k-step frags)
#define A_STAGE 16384
#define B_STAGE 16384
#define STAGE_BYTES (A_STAGE + B_STAGE)      // 32768
#define SMEM_TOTAL  (3 * STAGE_BYTES)        // 98304 (x2 CTA/SM = 192KB <= 228KB)

// ============================================================================
// Scratch: fp16 fragment-permuted copies (alloc guards -> __device__ globals)
// ============================================================================
__device__ __align__(1024) uint4 g_Ap[(size_t)(TOKENS / 16) * 64 * 32];      // 32MB
__device__ __align__(1024) uint4 g_Wp[(size_t)GROUPS * 32 * 128 * 32];       // 16MB

// ============================================================================
// Helpers (sm_80+ features only — plain sm_100 target rejects tcgen05)
// ============================================================================
__device__ __forceinline__ uint32_t smem_u32(const void* p) {
    uint32_t a;
    asm("{ .reg .u64 t; cvta.to.shared.u64 t, %1; cvt.u32.u64 %0, t; }" : "=r"(a) : "l"(p));
    return a;
}

__device__ __forceinline__ uint32_t pack_h2(float lo, float hi) {
    __half2 h = __halves2half2(__float2half_rn(lo), __float2half_rn(hi));
    return *reinterpret_cast<uint32_t*>(&h);
}

#define CP_ASYNC16(dst_u32, src_ptr) \
    asm volatile("cp.async.cg.shared.global [%0], [%1], 16;" \
                 :: "r"(dst_u32), "l"(src_ptr) : "memory")
#define CP_COMMIT() asm volatile("cp.async.commit_group;" ::: "memory")
#define CP_WAIT1()  asm volatile("cp.async.wait_group 1;" ::: "memory")
#define CP_WAIT0()  asm volatile("cp.async.wait_group 0;" ::: "memory")

#define LDS128(v, addr) \
    asm volatile("ld.shared.v4.u32 {%0,%1,%2,%3}, [%4];" \
                 : "=r"((v).x), "=r"((v).y), "=r"((v).z), "=r"((v).w) : "r"(addr))

// D += A*B  (m16n8k16 fp16 row.col, f32 accumulate)
#define MMA_F16(cc, a, b0, b1)                                                \
    asm volatile("mma.sync.aligned.m16n8k16.row.col.f32.f16.f16.f32 "         \
                 "{%0,%1,%2,%3}, {%4,%5,%6,%7}, {%8,%9}, {%0,%1,%2,%3};"      \
                 : "+f"((cc)[0]), "+f"((cc)[1]), "+f"((cc)[2]), "+f"((cc)[3]) \
                 : "r"((a).x), "r"((a).y), "r"((a).z), "r"((a).w),            \
                   "r"(b0), "r"(b1))

// ============================================================================
// Merged pre-pass (unchanged from R15 — measured 116.7us total with it):
//   blocks [0, 8192)      : A panels (16 rows x 128 cols)
//   blocks [8192, 10240)  : W panels (32 k x 128 n)
// ============================================================================
#define PREP_PAD  136
#define PREP_PAD2 132
#define PREP_A_BLOCKS ((TOKENS / 16) * (IN_F / 128))     // 8192
#define PREP_W_BLOCKS (GROUPS * 32 * 8)                  // 2048

__global__ void __launch_bounds__(256) prep_kernel(
    const float* __restrict__ A, const float* __restrict__ W,
    uint4* __restrict__ outA, uint4* __restrict__ outW)
{
    __shared__ float P[32 * PREP_PAD2];   // 16896B; covers both branches
    const int tid = threadIdx.x;

    if (blockIdx.x < PREP_A_BLOCKS) {
        // ---------------- A branch: 16 rows x 128 cols panel ----------------
        const int b      = blockIdx.x >> 3;
        const int colblk = blockIdx.x & 7;

#pragma unroll
        for (int t = 0; t < 2; t++) {
            int idx = tid + t * 256;
            int rr = idx >> 5, cc4 = idx & 31;
            float4 v = *reinterpret_cast<const float4*>(
                A + (size_t)(b * 16 + rr) * IN_F + colblk * 128 + cc4 * 4);
            float* dst = P + rr * PREP_PAD + cc4 * 4;
            dst[0] = v.x; dst[1] = v.y; dst[2] = v.z; dst[3] = v.w;
        }
        __syncthreads();

        const int ks   = tid >> 5;
        const int lane = tid & 31;
        const int g8   = lane >> 2;
        const int tig  = lane & 3;
        const int c0   = ks * 16 + 2 * tig;
        const float* r0 = P + g8 * PREP_PAD + c0;
        const float* r1 = r0 + 8 * PREP_PAD;
        uint4 v;
        v.x = pack_h2(r0[0], r0[1]);
        v.y = pack_h2(r1[0], r1[1]);
        v.z = pack_h2(r0[8], r0[9]);
        v.w = pack_h2(r1[8], r1[9]);
        outA[((size_t)b * 64 + colblk * 8 + ks) * 32 + lane] = v;
    } else {
        // ---------------- W branch: 32 k x 128 n panel ----------------------
        const int wb   = blockIdx.x - PREP_A_BLOCKS;
        const int g    = wb >> 8;
        const int kp   = (wb >> 3) & 31;
        const int ncol = wb & 7;

#pragma unroll
        for (int t = 0; t < 4; t++) {
            int idx = tid + t * 256;
            int rr = idx >> 5, cc4 = idx & 31;
            float4 v = *reinterpret_cast<const float4*>(
                W + ((size_t)g * IN_F + kp * 32 + rr) * OUT_F + ncol * 128 + cc4 * 4);
            float* dst = P + rr * PREP_PAD2 + cc4 * 4;
            dst[0] = v.x; dst[1] = v.y; dst[2] = v.z; dst[3] = v.w;
        }
        __syncthreads();

#pragma unroll
        for (int t = 0; t < 2; t++) {
            int o = tid + t * 256;
            int n8l = o >> 5, lane = o & 31;
            int g8 = lane >> 2, tig = lane & 3;
            const float* col = P + n8l * 8 + g8;
            const int k0 = 2 * tig;
            uint4 v;
            v.x = pack_h2(col[(k0     ) * PREP_PAD2], col[(k0 + 1 ) * PREP_PAD2]);
            v.y = pack_h2(col[(k0 + 8 ) * PREP_PAD2], col[(k0 + 9 ) * PREP_PAD2]);
            v.z = pack_h2(col[(k0 + 16) * PREP_PAD2], col[(k0 + 17) * PREP_PAD2]);
            v.w = pack_h2(col[(k0 + 24) * PREP_PAD2], col[(k0 + 25) * PREP_PAD2]);
            outW[(((size_t)g * 32 + kp) * 128 + ncol * 16 + n8l) * 32 + lane] = v;
        }
    }
}

// ============================================================================
// Main GEMM: 8 warps (2m x 4n), 64x32 warp tiles, fp16 m16n8k16.
// Same data layouts / pipeline as R13; only the warp decomposition changed.
// ============================================================================
__global__ void __launch_bounds__(THREADS, 2) grouped_gemm_kernel(
    const uint4* __restrict__ Ap,
    const uint4* __restrict__ Wp,
    const void* __restrict__ offsets_raw,
    float* __restrict__ out)
{
    extern __shared__ char smc[];
    const uint32_t sb = smem_u32(smc);

    const int tid  = threadIdx.x;
    const int wid  = tid >> 5;
    const int lane = tid & 31;
    const int g8   = lane >> 2;
    const int tig  = lane & 3;

    const int m_tile = blockIdx.x >> 3;
    const int n_tile = blockIdx.x & 7;
    const int row0   = m_tile * BM;
    const int n0     = n_tile * BN;

    // ---- expert group (dtype-robust: int32 or int64 offsets) --------------
    const int* offs32 = (const int*)offsets_raw;
    const bool is64 = (offs32[1] == 0);
    int g = 0;
    if (is64) {
        const long long* o64 = (const long long*)offsets_raw;
#pragma unroll
        for (int i = 0; i < GROUPS; i++)
            if (o64[i] <= (long long)row0) g = i + 1;
    } else {
#pragma unroll
        for (int i = 0; i < GROUPS; i++)
            if (offs32[i] <= row0) g = i + 1;
    }
    if (g > GROUPS - 1) g = GROUPS - 1;

    // ---- cp.async sources/dests (256 threads: 4 A + 4 B chunks each) ------
    // A stage linear = mblk*128 + ks*32 + lane; lin = tid + t*256 -> mblk += 2/t
    // B stage linear = kp*512 + n8*32 + lane;   lin = tid + j*256
    const uint4* a_src = Ap + ((size_t)m_tile * 8 + (tid >> 7)) * 2048 + (tid & 127);
    const uint4* b_src = Wp + (size_t)g * 131072 + n_tile * 512 + tid;
    const uint32_t a_dst = sb + (uint32_t)tid * 16u;
    const uint32_t b_dst = sb + (uint32_t)A_STAGE + (uint32_t)tid * 16u;

#define ISSUE_STAGE(c, so)                                                        \
    do {                                                                          \
        _Pragma("unroll")                                                         \
        for (int t = 0; t < 4; t++)                                               \
            CP_ASYNC16(a_dst + (so) + (uint32_t)(t * 4096),                       \
                       a_src + (size_t)t * 4096 + (c) * 128);                     \
        _Pragma("unroll")                                                         \
        for (int j = 0; j < 4; j++)                                               \
            CP_ASYNC16(b_dst + (so) + (uint32_t)(j * 4096),                       \
                       b_src + (size_t)(j >> 1) * 4096 + (j & 1) * 256 +          \
                           (size_t)(c) * 8192);                                   \
        CP_COMMIT();                                                              \
    } while (0)

    // ---- fragment SMEM bases ----------------------------------------------
    // A frag (mt 0..3, ks 0..3): aBase + mt*2048 + ks*512   (mblk = (wid>>2)*4+mt)
    // B frag (kp, nt 0..3):      bBase + kp*8192 + nt*512   (n8 = (wid&3)*4+nt)
    const uint32_t aBase = sb + (uint32_t)((wid >> 2) * 8192 + lane * 16);
    const uint32_t bBase = sb + (uint32_t)(A_STAGE + (wid & 3) * 2048 + lane * 16);

    float c[4][4][4];
#pragma unroll
    for (int mt = 0; mt < 4; mt++)
#pragma unroll
        for (int nt = 0; nt < 4; nt++)
#pragma unroll
            for (int q = 0; q < 4; q++) c[mt][nt][q] = 0.f;

    // ---- prologue: stages 0,1 ---------------------------------------------
    ISSUE_STAGE(0, 0u);
    ISSUE_STAGE(1, (uint32_t)STAGE_BYTES);

    // ---- main loop ---------------------------------------------------------
    for (int cidx = 0; cidx < NCHUNKS; cidx++) {
        if (cidx == NCHUNKS - 1) { CP_WAIT0(); } else { CP_WAIT1(); }
        __syncthreads();

        if (cidx + 2 < NCHUNKS) {
            int pc = cidx + 2;
            uint32_t so = (uint32_t)((pc % 3) * STAGE_BYTES);
            ISSUE_STAGE(pc, so);
        }

        const uint32_t so = (uint32_t)((cidx % 3) * STAGE_BYTES);
        const uint32_t sA = aBase + so;
        const uint32_t sB = bBase + so;

        uint4 bq[4];
        uint4 a[4];

        // kp0: ks0, ks1
#pragma unroll
        for (int nt = 0; nt < 4; nt++) LDS128(bq[nt], sB + nt * 512);
#pragma unroll
        for (int mt = 0; mt < 4; mt++) LDS128(a[mt], sA + mt * 2048);
#pragma unroll
        for (int mt = 0; mt < 4; mt++)
#pragma unroll
            for (int nt = 0; nt < 4; nt++)
                MMA_F16(c[mt][nt], a[mt], bq[nt].x, bq[nt].y);

#pragma unroll
        for (int mt = 0; mt < 4; mt++) LDS128(a[mt], sA + mt * 2048 + 512);
#pragma unroll
        for (int mt = 0; mt < 4; mt++)
#pragma unroll
            for (int nt = 0; nt < 4; nt++)
                MMA_F16(c[mt][nt], a[mt], bq[nt].z, bq[nt].w);

        // kp1: ks2, ks3
#pragma unroll
        for (int nt = 0; nt < 4; nt++) LDS128(bq[nt], sB + 8192 + nt * 512);
#pragma unroll
        for (int mt = 0; mt < 4; mt++) LDS128(a[mt], sA + mt * 2048 + 1024);
#pragma unroll
        for (int mt = 0; mt < 4; mt++)
#pragma unroll
            for (int nt = 0; nt < 4; nt++)
                MMA_F16(c[mt][nt], a[mt], bq[nt].x, bq[nt].y);

#pragma unroll
        for (int mt = 0; mt < 4; mt++) LDS128(a[mt], sA + mt * 2048 + 1536);
#pragma unroll
        for (int mt = 0; mt < 4; mt++)
#pragma unroll
            for (int nt = 0; nt < 4; nt++)
                MMA_F16(c[mt][nt], a[mt], bq[nt].z, bq[nt].w);
    }

    // ---- epilogue (fragment->gmem mapping verified R5/R8/R12) -------------
    const int mW = (wid >> 2) * 64;
    const int nW = (wid & 3) * 32;
#pragma unroll
    for (int mt = 0; mt < 4; mt++) {
        const int r = row0 + mW + mt * 16 + g8;
#pragma unroll
        for (int nt = 0; nt < 4; nt++) {
            const int colb = n0 + nW + nt * 8 + 2 * tig;
            float2 v0 = make_float2(c[mt][nt][0], c[mt][nt][1]);
            float2 v1 = make_float2(c[mt][nt][2], c[mt][nt][3]);
            *reinterpret_cast<float2*>(out + (size_t)r * OUT_F + colb)       = v0;
            *reinterpret_cast<float2*>(out + (size_t)(r + 8) * OUT_F + colb) = v1;
        }
    }
}

// ============================================================================
// Host side — no static guards; bind pointers by element count.
// ============================================================================
extern "C" void kernel_launch(void* const* d_in, const int* in_sizes, int n_in,
                              void* d_out, int out_size) {
    const float* hidden  = nullptr;
    const float* weight  = nullptr;
    const void*  offsets = nullptr;

    for (int i = 0; i < n_in; i++) {
        if (in_sizes[i] == TOKENS * IN_F)                hidden  = (const float*)d_in[i];
        else if (in_sizes[i] == GROUPS * IN_F * OUT_F)   weight  = (const float*)d_in[i];
        else                                             offsets = d_in[i];
    }
    float* out = (float*)d_out;

    void *aPtr = nullptr, *wPtr = nullptr;
    cudaGetSymbolAddress(&aPtr, g_Ap);
    cudaGetSymbolAddress(&wPtr, g_Wp);

    prep_kernel<<<PREP_A_BLOCKS + PREP_W_BLOCKS, 256>>>(
        hidden, weight, (uint4*)aPtr, (uint4*)wPtr);

    cudaFuncSetAttribute(grouped_gemm_kernel,
                         cudaFuncAttributeMaxDynamicSharedMemorySize, SMEM_TOTAL);
    grouped_gemm_kernel<<<M_TILES * N_TILES, THREADS, SMEM_TOTAL>>>(
        (const uint4*)aPtr, (const uint4*)wPtr, offsets, out);
}